// round 7
// baseline (speedup 1.0000x reference)
#include <cuda_runtime.h>
#include <cuda_bf16.h>
#include <cstdint>

#define NB   8            // b's per block (one warp per b)
#define TPB  256
#define EPS  1e-6f
typedef unsigned long long ull;

// dynamic smem layout (floats):
//   sRp  : [0, NB*576)            18432 B (R_pred slice)
//   gdup : [+NB*576, +240)          960 B (rot duplicated pairs, 80B per s)
//   sgt  : [+240, +NB*9)            288 B
#define OFF_RP    0
#define OFF_GDUP  (NB * 576)
#define OFF_GT    (OFF_GDUP + 240)
#define SMEM_FLOATS (OFF_GT + NB * 9)
#define SMEM_BYTES  (SMEM_FLOATS * 4)

__device__ float g_partial[8192];
__device__ unsigned int g_count = 0;    // self-resets via atomicInc wrap

__global__ __launch_bounds__(TPB, 4)
void geo_fused(const float* __restrict__ R_pred,
               const float* __restrict__ R_gt,
               const float* __restrict__ rot,
               float* __restrict__ out,
               int B, int grid, float invB)
{
    extern __shared__ float smem[];
    float* sRp  = smem + OFF_RP;
    float* gdup = smem + OFF_GDUP;
    float* sgt  = smem + OFF_GT;

    __shared__ float ssum;
    __shared__ int slast;
    __shared__ float warpsum[TPB / 32];

    const int tid = threadIdx.x;
    const int b0  = blockIdx.x * NB;
    const int nb  = min(NB, B - b0);
    const int n4  = nb * 144;

    // ---- 1) async coalesced staging of R_pred slice ----
    {
        const float4* src = reinterpret_cast<const float4*>(R_pred + (size_t)b0 * 576) + tid;
        uint32_t daddr = (uint32_t)__cvta_generic_to_shared(sRp) + tid * 16u;
        #pragma unroll
        for (int j = 0; j < 5; j++) {
            if (tid + j * TPB < n4)
                asm volatile("cp.async.cg.shared.global [%0], [%1], 16;"
                             :: "r"(daddr + j * (TPB * 16u)), "l"(src + j * TPB) : "memory");
        }
        asm volatile("cp.async.commit_group;" ::: "memory");
    }

    // ---- 2) small tables while the copy flies ----
    if (tid < 108) {
        int s = tid / 9, e = tid - s * 9;
        float v = __ldg(rot + tid);
        gdup[s * 20 + e * 2]     = v;
        gdup[s * 20 + e * 2 + 1] = v;
    }
    if (tid < nb * 9) sgt[tid] = __ldg(R_gt + (size_t)b0 * 9 + tid);
    if (tid == 0) ssum = 0.0f;

    asm volatile("cp.async.wait_group 0;" ::: "memory");
    __syncthreads();

    // ---- 3) compute: one warp per b, 2 candidates per lane ----
    const int bl   = tid >> 5;            // warp id = local b
    const int lane = tid & 31;
    float cmax = -1e30f;

    if (bl < nb) {
        float g[9];
        const float* gt = sgt + bl * 9;
        #pragma unroll
        for (int k = 0; k < 9; k++) g[k] = gt[k];   // broadcast LDS

        // 2 candidates = 18 floats at 72B lane stride; 9 conflict-free LDS.64
        float rp[18];
        const float2* p2 = reinterpret_cast<const float2*>(&sRp[(bl * 64 + lane * 2) * 9]);
        #pragma unroll
        for (int k = 0; k < 9; k++) {
            float2 v = p2[k];
            rp[2*k] = v.x; rp[2*k+1] = v.y;
        }

        // M[c][i*3+k] = sum_j rp[c,i,j]*g[k*3+j]; pack pair (c0,c1)
        ull a[9];
        #pragma unroll
        for (int e = 0; e < 9; e++) {
            const int i3 = (e / 3) * 3, k3 = (e % 3) * 3;
            float m0 = fmaf(rp[i3+2],   g[k3+2], fmaf(rp[i3+1],   g[k3+1], rp[i3]   * g[k3]));
            float m1 = fmaf(rp[9+i3+2], g[k3+2], fmaf(rp[9+i3+1], g[k3+1], rp[9+i3] * g[k3]));
            asm("mov.b64 %0, {%1, %2};" : "=l"(a[e]) : "f"(m0), "f"(m1));
        }

        // s-loop: tr[pair,s] = <rot[s], M> via duplicated-pair f32x2, 2 chains
        #pragma unroll
        for (int s = 0; s < 12; s++) {
            const ull* gp = reinterpret_cast<const ull*>(gdup + s * 20);
            ull gs[9];
            #pragma unroll
            for (int h = 0; h < 4; h++) {          // broadcast LDS.128
                ulonglong2 q = reinterpret_cast<const ulonglong2*>(gp)[h];
                gs[2*h] = q.x; gs[2*h+1] = q.y;
            }
            gs[8] = gp[8];

            ull acc0 = 0ull, acc1 = 0ull;
            #pragma unroll
            for (int e = 0; e < 5; e++)
                asm("fma.rn.f32x2 %0, %1, %2, %3;" : "=l"(acc0) : "l"(a[e]), "l"(gs[e]), "l"(acc0));
            #pragma unroll
            for (int e = 5; e < 9; e++)
                asm("fma.rn.f32x2 %0, %1, %2, %3;" : "=l"(acc1) : "l"(a[e]), "l"(gs[e]), "l"(acc1));
            ull acc;
            asm("add.rn.f32x2 %0, %1, %2;" : "=l"(acc) : "l"(acc0), "l"(acc1));
            float2 f = *reinterpret_cast<float2*>(&acc);
            cmax = fmaxf(cmax, fmaxf(f.x, f.y));
        }
    }

    // full-warp max (all 32 lanes share one b)
    #pragma unroll
    for (int w = 16; w >= 1; w >>= 1)
        cmax = fmaxf(cmax, __shfl_xor_sync(0xFFFFFFFFu, cmax, w));

    if (lane == 0 && bl < nb) {
        float cosv = (cmax - 1.0f) * 0.5f;
        cosv = fminf(fmaxf(cosv, -1.0f + EPS), 1.0f - EPS);
        atomicAdd(&ssum, acosf(cosv));      // 8 shared atomics per block
    }
    __syncthreads();

    // ---- 4) publish partial; last block reduces (counter wraps to 0) ----
    if (tid == 0) {
        g_partial[blockIdx.x] = ssum;
        __threadfence();
        unsigned int old = atomicInc(&g_count, (unsigned int)(grid - 1));
        slast = (old == (unsigned int)(grid - 1));
    }
    __syncthreads();

    if (slast) {
        float v = 0.0f;
        for (int i = tid; i < grid; i += TPB) v += __ldcg(&g_partial[i]);
        #pragma unroll
        for (int w = 16; w >= 1; w >>= 1)
            v += __shfl_xor_sync(0xFFFFFFFFu, v, w);
        if ((tid & 31) == 0) warpsum[tid >> 5] = v;
        __syncthreads();
        if (tid < TPB / 32) {
            float w2 = warpsum[tid];
            #pragma unroll
            for (int w = TPB / 64; w >= 1; w >>= 1)
                w2 += __shfl_xor_sync(0xFFu, w2, w);
            if (tid == 0) out[0] = w2 * invB;
        }
    }
}

extern "C" void kernel_launch(void* const* d_in, const int* in_sizes, int n_in,
                              void* d_out, int out_size)
{
    const float* R_pred = (const float*)d_in[0];
    const float* R_gt   = (const float*)d_in[1];
    const float* rot    = (const float*)d_in[2];
    float* out = (float*)d_out;

    const int B = in_sizes[1] / 9;
    const int grid = (B + NB - 1) / NB;

    cudaFuncSetAttribute(geo_fused, cudaFuncAttributeMaxDynamicSharedMemorySize, SMEM_BYTES);
    geo_fused<<<grid, TPB, SMEM_BYTES>>>(R_pred, R_gt, rot, out, B, grid, 1.0f / (float)B);
}

// round 8
// speedup vs baseline: 1.3937x; 1.3937x over previous
#include <cuda_runtime.h>
#include <cuda_bf16.h>
#include <cstdint>

#define NB   8            // b's per block
#define TPB  128          // 16 threads per b, 4 candidates per thread
#define EPS  1e-6f
typedef unsigned long long ull;

// dynamic smem layout (floats):
//   sRp  : [0, NB*576)            18432 B (R_pred slice, candidate-major)
//   gdup : [+NB*576, +240)          960 B (rot duplicated pairs, 80B per s)
//   sgt  : [+240, +NB*9)            288 B
#define OFF_RP    0
#define OFF_GDUP  (NB * 576)
#define OFF_GT    (OFF_GDUP + 240)
#define SMEM_FLOATS (OFF_GT + NB * 9)
#define SMEM_BYTES  (SMEM_FLOATS * 4)

__device__ float g_partial[8192];
__device__ unsigned int g_count = 0;    // self-resets via atomicInc wrap

__global__ __launch_bounds__(TPB, 8)
void geo_fused(const float* __restrict__ R_pred,
               const float* __restrict__ R_gt,
               const float* __restrict__ rot,
               float* __restrict__ out,
               int B, int grid, float invB)
{
    extern __shared__ float smem[];
    float* sRp  = smem + OFF_RP;
    float* gdup = smem + OFF_GDUP;
    float* sgt  = smem + OFF_GT;

    __shared__ float ssum;
    __shared__ int slast;

    const int tid = threadIdx.x;
    const int b0  = blockIdx.x * NB;
    const int nb  = min(NB, B - b0);
    const int n4  = nb * 144;             // float4 count (1152 when nb==8)

    // ---- 1) async coalesced staging of R_pred slice (9 x 16B per thread) ----
    {
        const float4* src = reinterpret_cast<const float4*>(R_pred + (size_t)b0 * 576) + tid;
        uint32_t daddr = (uint32_t)__cvta_generic_to_shared(sRp) + tid * 16u;
        #pragma unroll
        for (int j = 0; j < 9; j++) {
            if (tid + j * TPB < n4)
                asm volatile("cp.async.cg.shared.global [%0], [%1], 16;"
                             :: "r"(daddr + j * (TPB * 16u)), "l"(src + j * TPB) : "memory");
        }
        asm volatile("cp.async.commit_group;" ::: "memory");
    }

    // ---- 2) small tables while the copy flies ----
    if (tid < 108) {
        int s = tid / 9, e = tid - s * 9;
        float v = __ldg(rot + tid);
        gdup[s * 20 + e * 2]     = v;
        gdup[s * 20 + e * 2 + 1] = v;
    }
    if (tid < nb * 9) sgt[tid] = __ldg(R_gt + (size_t)b0 * 9 + tid);
    if (tid == 0) ssum = 0.0f;

    asm volatile("cp.async.wait_group 0;" ::: "memory");
    __syncthreads();

    // ---- 3) main compute: 4 candidates per thread (amortizes the rot loads) ----
    const int bl = tid >> 4;
    const int m  = tid & 15;
    float cmax = -1e30f;

    if (bl < nb) {
        float g[9];
        const float* gt = sgt + bl * 9;
        #pragma unroll
        for (int k = 0; k < 9; k++) g[k] = gt[k];   // broadcast LDS

        // 4 candidates = 9 conflict-free LDS.128 (4-phase, banks disjoint)
        float rp[36];
        const float4* p4 = reinterpret_cast<const float4*>(&sRp[(bl * 64 + m * 4) * 9]);
        #pragma unroll
        for (int k = 0; k < 9; k++) {
            float4 v = p4[k];
            rp[4*k+0] = v.x; rp[4*k+1] = v.y; rp[4*k+2] = v.z; rp[4*k+3] = v.w;
        }

        // M[c][i*3+k] = sum_j rp[c,i,j]*g[k*3+j]; pack candidate pairs
        ull a[9], bq[9];
        #pragma unroll
        for (int e = 0; e < 9; e++) {
            const int i3 = (e / 3) * 3, k3 = (e % 3) * 3;
            float m0 = fmaf(rp[ 0+i3+2], g[k3+2], fmaf(rp[ 0+i3+1], g[k3+1], rp[ 0+i3] * g[k3]));
            float m1 = fmaf(rp[ 9+i3+2], g[k3+2], fmaf(rp[ 9+i3+1], g[k3+1], rp[ 9+i3] * g[k3]));
            float m2 = fmaf(rp[18+i3+2], g[k3+2], fmaf(rp[18+i3+1], g[k3+1], rp[18+i3] * g[k3]));
            float m3 = fmaf(rp[27+i3+2], g[k3+2], fmaf(rp[27+i3+1], g[k3+1], rp[27+i3] * g[k3]));
            asm("mov.b64 %0, {%1, %2};" : "=l"(a[e])  : "f"(m0), "f"(m1));
            asm("mov.b64 %0, {%1, %2};" : "=l"(bq[e]) : "f"(m2), "f"(m3));
        }

        // s-loop: tr[c,s] = <rot[s], M[c]> via duplicated-pair f32x2
        #pragma unroll
        for (int s = 0; s < 12; s++) {
            const ull* gp = reinterpret_cast<const ull*>(gdup + s * 20);
            ull acc0 = 0ull, acc1 = 0ull;
            #pragma unroll
            for (int h = 0; h < 4; h++) {           // broadcast LDS.128
                ulonglong2 q = reinterpret_cast<const ulonglong2*>(gp)[h];
                asm("fma.rn.f32x2 %0, %1, %2, %3;" : "=l"(acc0) : "l"(a[2*h]),    "l"(q.x), "l"(acc0));
                asm("fma.rn.f32x2 %0, %1, %2, %3;" : "=l"(acc1) : "l"(bq[2*h]),   "l"(q.x), "l"(acc1));
                asm("fma.rn.f32x2 %0, %1, %2, %3;" : "=l"(acc0) : "l"(a[2*h+1]),  "l"(q.y), "l"(acc0));
                asm("fma.rn.f32x2 %0, %1, %2, %3;" : "=l"(acc1) : "l"(bq[2*h+1]), "l"(q.y), "l"(acc1));
            }
            ull g8 = gp[8];
            asm("fma.rn.f32x2 %0, %1, %2, %3;" : "=l"(acc0) : "l"(a[8]),  "l"(g8), "l"(acc0));
            asm("fma.rn.f32x2 %0, %1, %2, %3;" : "=l"(acc1) : "l"(bq[8]), "l"(g8), "l"(acc1));

            float2 f0 = *reinterpret_cast<float2*>(&acc0);
            float2 f1 = *reinterpret_cast<float2*>(&acc1);
            cmax = fmaxf(cmax, fmaxf(fmaxf(f0.x, f0.y), fmaxf(f1.x, f1.y)));
        }
    }

    // max over the 16 lanes sharing this b
    #pragma unroll
    for (int w = 8; w >= 1; w >>= 1)
        cmax = fmaxf(cmax, __shfl_xor_sync(0xFFFFFFFFu, cmax, w));

    if (m == 0 && bl < nb) {
        float cosv = (cmax - 1.0f) * 0.5f;
        cosv = fminf(fmaxf(cosv, -1.0f + EPS), 1.0f - EPS);
        atomicAdd(&ssum, acosf(cosv));      // 8 shared atomics per block
    }
    __syncthreads();

    // ---- 4) publish partial; last block reduces (counter wraps to 0) ----
    if (tid == 0) {
        g_partial[blockIdx.x] = ssum;
        __threadfence();
        unsigned int old = atomicInc(&g_count, (unsigned int)(grid - 1));
        slast = (old == (unsigned int)(grid - 1));
    }
    __syncthreads();

    if (slast) {
        __shared__ float warpsum[TPB / 32];
        float v = 0.0f;
        for (int i = tid; i < grid; i += TPB) v += __ldcg(&g_partial[i]);
        #pragma unroll
        for (int w = 16; w >= 1; w >>= 1)
            v += __shfl_xor_sync(0xFFFFFFFFu, v, w);
        if ((tid & 31) == 0) warpsum[tid >> 5] = v;
        __syncthreads();
        if (tid < TPB / 32) {
            float w2 = warpsum[tid];
            #pragma unroll
            for (int w = TPB / 64; w >= 1; w >>= 1)
                w2 += __shfl_xor_sync(0xFFu, w2, w);
            if (tid == 0) out[0] = w2 * invB;
        }
    }
}

extern "C" void kernel_launch(void* const* d_in, const int* in_sizes, int n_in,
                              void* d_out, int out_size)
{
    const float* R_pred = (const float*)d_in[0];
    const float* R_gt   = (const float*)d_in[1];
    const float* rot    = (const float*)d_in[2];
    float* out = (float*)d_out;

    const int B = in_sizes[1] / 9;
    const int grid = (B + NB - 1) / NB;

    cudaFuncSetAttribute(geo_fused, cudaFuncAttributeMaxDynamicSharedMemorySize, SMEM_BYTES);
    geo_fused<<<grid, TPB, SMEM_BYTES>>>(R_pred, R_gt, rot, out, B, grid, 1.0f / (float)B);
}